// round 1
// baseline (speedup 1.0000x reference)
#include <cuda_runtime.h>
#include <cuda_bf16.h>
#include <math.h>

// ----------------------------------------------------------------------------
// Attention_13314398617962
// t=512, b=64, s=1024, hu=1024.
//   scores[t,b] = MLP(concat(si[b], h[t,b]))   (2048 -> 10 -> 5 -> 1, BN+relu)
//   a = softmax(scores.flatten())              (over all 32768)
//   ci[b,:] = sum_tau a[tau] * h[tau, b, :]    (tau < 512)
// ----------------------------------------------------------------------------

#define T_DIM 512
#define B_DIM 64
#define HU 1024
#define NROWS (T_DIM * B_DIM)   // 32768
#define RPB 32                  // rows per block in score kernel

__device__ float g_pre0[B_DIM * 10];   // si @ W0[:1024] per b
__device__ float g_ep[30];             // s0[10] t0[10] s1[5] t1[5]
__device__ float g_scores[NROWS];
__device__ float g_w[T_DIM];           // softmax weights for tau < 512

// ---------------------------------------------------------------------------
// K0: per-b si contribution + folded BN constants
// grid: 64 blocks x 320 threads (10 warps; warp j computes pre0[b][j])
// ---------------------------------------------------------------------------
__global__ void prep_kernel(const float* __restrict__ si,
                            const float* __restrict__ W0,
                            const float* __restrict__ b0,
                            const float* __restrict__ g0,
                            const float* __restrict__ be0,
                            const float* __restrict__ m0,
                            const float* __restrict__ v0,
                            const float* __restrict__ b1,
                            const float* __restrict__ g1,
                            const float* __restrict__ be1,
                            const float* __restrict__ m1,
                            const float* __restrict__ v1)
{
    int b = blockIdx.x;
    int tid = threadIdx.x;
    int w = tid >> 5;     // 0..9 = output column
    int l = tid & 31;

    const float* sb = si + b * 1024;
    float acc = 0.f;
#pragma unroll 8
    for (int i = 0; i < 32; ++i) {
        int k = l + (i << 5);
        acc = fmaf(sb[k], W0[k * 10 + w], acc);
    }
#pragma unroll
    for (int o = 16; o > 0; o >>= 1)
        acc += __shfl_xor_sync(0xffffffffu, acc, o);
    if (l == 0) g_pre0[b * 10 + w] = acc;

    if (b == 0) {
        if (tid < 10) {
            float s = g0[tid] * (1.0f / sqrtf(v0[tid] + 1e-5f));
            g_ep[tid] = s;
            g_ep[10 + tid] = (b0[tid] - m0[tid]) * s + be0[tid];
        } else if (tid >= 16 && tid < 21) {
            int i = tid - 16;
            float s = g1[i] * (1.0f / sqrtf(v1[i] + 1e-5f));
            g_ep[20 + i] = s;
            g_ep[25 + i] = (b1[i] - m1[i]) * s + be1[i];
        }
    }
}

// ---------------------------------------------------------------------------
// K1: scores for all 32768 rows.
// 256 threads = 2 row-groups of 128 threads (4 warps each).
// Thread ts (0..127) owns k = 4*ts..4*ts+3 and 512+4*ts..+3 (8 k, 80 wregs).
// 2-round shfl reduce -> 32 smem partials per j -> rotating epilogue warp.
// ---------------------------------------------------------------------------
__global__ __launch_bounds__(256, 2)
void score_kernel(const float* __restrict__ h,
                  const float* __restrict__ W0,
                  const float* __restrict__ W1,
                  const float* __restrict__ W2,
                  const float* __restrict__ b2)
{
    __shared__ float red[2][2][320];      // [buf][g][(wlocal*8+q)*10 + j]
    __shared__ float pre0s[RPB * 10];
    __shared__ float epi[86];             // s0[10] t0[10] s1[5] t1[5] W1[50] W2[5] b2

    int tid    = threadIdx.x;
    int g      = tid >> 7;                // row group 0/1
    int ts     = tid & 127;
    int lane   = tid & 31;
    int warp   = tid >> 5;
    int wlocal = warp & 3;
    int rowbase = blockIdx.x * RPB;
    int bbase   = rowbase & 63;

    // stage epilogue constants
    if (tid < 30)                  epi[tid] = g_ep[tid];
    if (tid >= 32 && tid < 82)     epi[30 + tid - 32] = W1[tid - 32];
    if (tid >= 96 && tid < 101)    epi[80 + tid - 96] = W2[tid - 96];
    if (tid == 101)                epi[85] = b2[0];
    for (int i = tid; i < RPB * 10; i += 256)
        pre0s[i] = g_pre0[bbase * 10 + i];

    // register-resident weights: wreg[kk*10+j] for local kk (4 lo-half, 4 hi-half)
    float wreg[80];
    {
        const float* wp0 = W0 + (1024 + 4 * ts) * 10;        // 40 consecutive floats
        const float* wp1 = W0 + (1024 + 512 + 4 * ts) * 10;
#pragma unroll
        for (int i = 0; i < 10; ++i)
            reinterpret_cast<float4*>(wreg)[i] = reinterpret_cast<const float4*>(wp0)[i];
#pragma unroll
        for (int i = 0; i < 10; ++i)
            reinterpret_cast<float4*>(wreg + 40)[i] = reinterpret_cast<const float4*>(wp1)[i];
    }

    // 2-deep row prefetch
    const float* hb = h + (size_t)(rowbase + g) * 1024 + 4 * ts;
    float4 A0 = *reinterpret_cast<const float4*>(hb);
    float4 B0 = *reinterpret_cast<const float4*>(hb + 512);
    float4 A1 = *reinterpret_cast<const float4*>(hb + 2048);
    float4 B1 = *reinterpret_cast<const float4*>(hb + 2048 + 512);

    __syncthreads();   // smem staging visible

#pragma unroll 2
    for (int it = 0; it < RPB / 2; ++it) {
        float4 ca = A0, cb = B0;
        A0 = A1; B0 = B1;
        if (it < RPB / 2 - 2) {
            const float* pn = hb + (size_t)(it + 2) * 2048;
            A1 = *reinterpret_cast<const float4*>(pn);
            B1 = *reinterpret_cast<const float4*>(pn + 512);
        }

        float p[10];
#pragma unroll
        for (int j = 0; j < 10; ++j) {
            float a = ca.x * wreg[j];
            a = fmaf(ca.y, wreg[10 + j], a);
            a = fmaf(ca.z, wreg[20 + j], a);
            a = fmaf(ca.w, wreg[30 + j], a);
            a = fmaf(cb.x, wreg[40 + j], a);
            a = fmaf(cb.y, wreg[50 + j], a);
            a = fmaf(cb.z, wreg[60 + j], a);
            a = fmaf(cb.w, wreg[70 + j], a);
            p[j] = a;
        }

        // 2-round reduce -> mod-8 residue classes
#pragma unroll
        for (int j = 0; j < 10; ++j) {
            p[j] += __shfl_xor_sync(0xffffffffu, p[j], 16);
            p[j] += __shfl_xor_sync(0xffffffffu, p[j], 8);
        }
        int buf = it & 1;
        if (lane < 8) {
            float* rb = &red[buf][g][(wlocal * 8 + lane) * 10];
#pragma unroll
            for (int j = 0; j < 10; ++j) rb[j] = p[j];
        }
        __syncthreads();

        // rotating epilogue warp per group
        if (wlocal == (it & 3)) {
            int rloc = 2 * it + g;
            int row  = rowbase + rloc;
            float d = 0.f;
            if (lane < 10) {
                const float* rb = &red[buf][g][0];
#pragma unroll
                for (int q = 0; q < 32; ++q) d += rb[q * 10 + lane];
                d += pre0s[rloc * 10 + lane];
                d = fmaxf(fmaf(d, epi[lane], epi[10 + lane]), 0.f);   // BN0 + relu
            }
            float z = 0.f;
#pragma unroll
            for (int j = 0; j < 10; ++j) {
                float aj = __shfl_sync(0xffffffffu, d, j);
                float w1v = (lane < 5) ? epi[30 + j * 5 + lane] : 0.f;
                z = fmaf(aj, w1v, z);
            }
            float v = 0.f;
            if (lane < 5)
                v = fmaxf(fmaf(z, epi[20 + lane], epi[25 + lane]), 0.f) * epi[80 + lane];
            v += __shfl_xor_sync(0xffffffffu, v, 1);
            v += __shfl_xor_sync(0xffffffffu, v, 2);
            v += __shfl_xor_sync(0xffffffffu, v, 4);
            if (lane == 0) g_scores[row] = v + epi[85];
        }
    }
}

// ---------------------------------------------------------------------------
// K2: global softmax stats (max + sum of exp) over 32768 scores, write w[0:512]
// Single block of 1024 threads (deterministic).
// ---------------------------------------------------------------------------
__global__ void softmax_kernel()
{
    __shared__ float sred[1024];
    int tid = threadIdx.x;

    float vals[32];
    float m = -1e30f;
#pragma unroll
    for (int i = 0; i < 32; ++i) {
        vals[i] = g_scores[tid + (i << 10)];
        m = fmaxf(m, vals[i]);
    }
    sred[tid] = m;
    __syncthreads();
    for (int s = 512; s > 0; s >>= 1) {
        if (tid < s) sred[tid] = fmaxf(sred[tid], sred[tid + s]);
        __syncthreads();
    }
    float M = sred[0];
    __syncthreads();

    float sum = 0.f;
#pragma unroll
    for (int i = 0; i < 32; ++i) sum += expf(vals[i] - M);
    sred[tid] = sum;
    __syncthreads();
    for (int s = 512; s > 0; s >>= 1) {
        if (tid < s) sred[tid] += sred[tid + s];
        __syncthreads();
    }
    float inv = 1.0f / sred[0];

    if (tid < T_DIM)
        g_w[tid] = expf(vals[0] - M) * inv;   // vals[0] == g_scores[tid]
}

// ---------------------------------------------------------------------------
// K3: ci[b,:] = sum_tau w[tau] * h[tau,b,:]
// grid (16 hid-chunks of 64, 64 b) x 128 threads; tg = tau residue mod 8.
// ---------------------------------------------------------------------------
__global__ __launch_bounds__(128)
void wsum_kernel(const float* __restrict__ h, float* __restrict__ out)
{
    __shared__ float  ws[T_DIM];
    __shared__ float4 part[8][16];

    int tid = threadIdx.x;
    int c = blockIdx.x;           // hid chunk
    int b = blockIdx.y;
    int tg = tid >> 4;            // 0..7
    int s  = tid & 15;            // 0..15

    reinterpret_cast<float4*>(ws)[tid] =
        reinterpret_cast<const float4*>(g_w)[tid];   // 512 floats
    __syncthreads();

    const float* hp = h + (size_t)b * 1024 + c * 64 + 4 * s;
    float4 acc = make_float4(0.f, 0.f, 0.f, 0.f);
#pragma unroll 4
    for (int t = tg; t < T_DIM; t += 8) {
        float4 hv = *reinterpret_cast<const float4*>(hp + (size_t)t * (B_DIM * HU));
        float w = ws[t];
        acc.x = fmaf(w, hv.x, acc.x);
        acc.y = fmaf(w, hv.y, acc.y);
        acc.z = fmaf(w, hv.z, acc.z);
        acc.w = fmaf(w, hv.w, acc.w);
    }
    if (tg) part[tg][s] = acc;
    __syncthreads();
    if (tg == 0) {
#pragma unroll
        for (int q = 1; q < 8; ++q) {
            float4 pv = part[q][s];
            acc.x += pv.x; acc.y += pv.y; acc.z += pv.z; acc.w += pv.w;
        }
        *reinterpret_cast<float4*>(out + b * 1024 + c * 64 + 4 * s) = acc;
    }
}

// ---------------------------------------------------------------------------
extern "C" void kernel_launch(void* const* d_in, const int* in_sizes, int n_in,
                              void* d_out, int out_size)
{
    const float* si  = (const float*)d_in[0];
    const float* h   = (const float*)d_in[1];
    const float* W0  = (const float*)d_in[2];
    const float* b0  = (const float*)d_in[3];
    const float* g0  = (const float*)d_in[4];
    const float* be0 = (const float*)d_in[5];
    const float* m0  = (const float*)d_in[6];
    const float* v0  = (const float*)d_in[7];
    const float* W1  = (const float*)d_in[8];
    const float* b1  = (const float*)d_in[9];
    const float* g1  = (const float*)d_in[10];
    const float* be1 = (const float*)d_in[11];
    const float* m1  = (const float*)d_in[12];
    const float* v1  = (const float*)d_in[13];
    const float* W2  = (const float*)d_in[14];
    const float* b2  = (const float*)d_in[15];
    float* out = (float*)d_out;

    prep_kernel<<<B_DIM, 320>>>(si, W0, b0, g0, be0, m0, v0, b1, g1, be1, m1, v1);
    score_kernel<<<NROWS / RPB, 256>>>(h, W0, W1, W2, b2);
    softmax_kernel<<<1, 1024>>>();
    wsum_kernel<<<dim3(16, B_DIM), 128>>>(h, out);
}

// round 2
// speedup vs baseline: 1.0767x; 1.0767x over previous
#include <cuda_runtime.h>
#include <cuda_bf16.h>
#include <math.h>

// ----------------------------------------------------------------------------
// Attention_13314398617962   (t=512, b=64, s=1024, hu=1024)
//   scores[t,b] = MLP(concat(si[b], h[t,b]))   (2048 -> 10 -> 5 -> 1, BN+relu)
//   a = softmax(scores.flatten())              (over all 32768)
//   ci[b,:] = sum_tau a[tau] * h[tau, b, :]    (tau < 512)
// ----------------------------------------------------------------------------

#define T_DIM 512
#define B_DIM 64
#define HU 1024
#define NROWS (T_DIM * B_DIM)   // 32768
#define RPB 32                  // rows per block in score kernel

__device__ float g_pre0[B_DIM * 10];   // si @ W0[:1024] per b
__device__ float g_ep[30];             // s0[10] t0[10] s1[5] t1[5]
__device__ float g_scores[NROWS];
__device__ float g_w[T_DIM];           // softmax weights for tau < 512
__device__ float g_pmax[32];
__device__ float g_psum[32];

// ---------------------------------------------------------------------------
// K0: per-b si contribution + folded BN constants
// ---------------------------------------------------------------------------
__global__ void prep_kernel(const float* __restrict__ si,
                            const float* __restrict__ W0,
                            const float* __restrict__ b0,
                            const float* __restrict__ g0,
                            const float* __restrict__ be0,
                            const float* __restrict__ m0,
                            const float* __restrict__ v0,
                            const float* __restrict__ b1,
                            const float* __restrict__ g1,
                            const float* __restrict__ be1,
                            const float* __restrict__ m1,
                            const float* __restrict__ v1)
{
    int b = blockIdx.x;
    int tid = threadIdx.x;
    int w = tid >> 5;     // 0..9 = output column
    int l = tid & 31;

    const float* sb = si + b * 1024;
    float acc = 0.f;
#pragma unroll 8
    for (int i = 0; i < 32; ++i) {
        int k = l + (i << 5);
        acc = fmaf(sb[k], W0[k * 10 + w], acc);
    }
#pragma unroll
    for (int o = 16; o > 0; o >>= 1)
        acc += __shfl_xor_sync(0xffffffffu, acc, o);
    if (l == 0) g_pre0[b * 10 + w] = acc;

    if (b == 0) {
        if (tid < 10) {
            float s = g0[tid] * (1.0f / sqrtf(v0[tid] + 1e-5f));
            g_ep[tid] = s;
            g_ep[10 + tid] = (b0[tid] - m0[tid]) * s + be0[tid];
        } else if (tid >= 16 && tid < 21) {
            int i = tid - 16;
            float s = g1[i] * (1.0f / sqrtf(v1[i] + 1e-5f));
            g_ep[20 + i] = s;
            g_ep[25 + i] = (b1[i] - m1[i]) * s + be1[i];
        }
    }
}

// ---------------------------------------------------------------------------
// K1: scores for 32 rows/block. 256 threads = 2 row-groups (g) of 128.
// Thread ts owns k = 4*ts..+3 and 512+4*ts..+3 (80 weight regs).
// NO barrier in the hot loop: each iteration's 32x10 partials go to a
// distinct smem slot; one barrier at the end, block-wide reduce, then a
// 32-thread fused BN/MLP epilogue.
// ---------------------------------------------------------------------------
__global__ __launch_bounds__(256, 2)
void score_kernel(const float* __restrict__ h,
                  const float* __restrict__ W0,
                  const float* __restrict__ W1,
                  const float* __restrict__ W2,
                  const float* __restrict__ b2)
{
    __shared__ float red[2 * 16 * 32 * 10];   // [g][it][part][j]  40 KB
    __shared__ float pre0s[RPB * 10];
    __shared__ float dsum[RPB * 10];
    __shared__ float epi[86];                 // s0 t0 s1 t1 W1[50] W2[5] b2

    int tid    = threadIdx.x;
    int g      = tid >> 7;
    int ts     = tid & 127;
    int lane   = tid & 31;
    int wlocal = (tid >> 5) & 3;
    int rowbase = blockIdx.x * RPB;
    int bbase   = rowbase & 63;

    if (tid < 30)                  epi[tid] = g_ep[tid];
    if (tid >= 32 && tid < 82)     epi[30 + tid - 32] = W1[tid - 32];
    if (tid >= 96 && tid < 101)    epi[80 + tid - 96] = W2[tid - 96];
    if (tid == 101)                epi[85] = b2[0];
    if (tid < 160) {
        pre0s[tid] = g_pre0[bbase * 10 + tid];
        pre0s[160 + tid] = g_pre0[bbase * 10 + 160 + tid];
    }

    // register-resident weights: wreg[kk*10+j]
    float wreg[80];
    {
        const float* wp0 = W0 + (1024 + 4 * ts) * 10;
        const float* wp1 = W0 + (1024 + 512 + 4 * ts) * 10;
#pragma unroll
        for (int i = 0; i < 10; ++i)
            reinterpret_cast<float4*>(wreg)[i] = reinterpret_cast<const float4*>(wp0)[i];
#pragma unroll
        for (int i = 0; i < 10; ++i)
            reinterpret_cast<float4*>(wreg + 40)[i] = reinterpret_cast<const float4*>(wp1)[i];
    }

    const float* hb = h + (size_t)(rowbase + g) * 1024 + 4 * ts;
    float4 A0 = *reinterpret_cast<const float4*>(hb);
    float4 B0 = *reinterpret_cast<const float4*>(hb + 512);
    float4 A1 = *reinterpret_cast<const float4*>(hb + 2048);
    float4 B1 = *reinterpret_cast<const float4*>(hb + 2048 + 512);

    float* myred = red + ((g * 16) * 32 + wlocal * 8 + lane) * 10;

#pragma unroll 2
    for (int it = 0; it < 16; ++it) {
        float4 ca = A0, cb = B0;
        A0 = A1; B0 = B1;
        if (it < 14) {
            const float* pn = hb + (size_t)(it + 2) * 2048;
            A1 = *reinterpret_cast<const float4*>(pn);
            B1 = *reinterpret_cast<const float4*>(pn + 512);
        }

        float p[10];
#pragma unroll
        for (int j = 0; j < 10; ++j) {
            float a = ca.x * wreg[j];
            a = fmaf(ca.y, wreg[10 + j], a);
            a = fmaf(ca.z, wreg[20 + j], a);
            a = fmaf(ca.w, wreg[30 + j], a);
            a = fmaf(cb.x, wreg[40 + j], a);
            a = fmaf(cb.y, wreg[50 + j], a);
            a = fmaf(cb.z, wreg[60 + j], a);
            a = fmaf(cb.w, wreg[70 + j], a);
            p[j] = a;
        }
#pragma unroll
        for (int j = 0; j < 10; ++j) {
            p[j] += __shfl_xor_sync(0xffffffffu, p[j], 16);
            p[j] += __shfl_xor_sync(0xffffffffu, p[j], 8);
        }
        if (lane < 8) {
            float* rb = myred + it * 320;
#pragma unroll
            for (int j = 0; j < 10; ++j) rb[j] = p[j];
        }
    }
    __syncthreads();

    // block reduce: 320 (row,j) sums, each over 32 partials
#pragma unroll
    for (int pass = 0; pass < 2; ++pass) {
        int m = tid + pass * 256;
        if (m < 320) {
            int gg = m / 160;
            int rem = m - gg * 160;
            int rl = rem / 10;
            int j = rem - rl * 10;
            const float* base = red + ((gg * 16 + rl) * 32) * 10 + j;
            float s = 0.f;
#pragma unroll
            for (int q = 0; q < 32; ++q) s += base[q * 10];
            dsum[(2 * rl + gg) * 10 + j] = s;
        }
    }
    __syncthreads();

    // fused BN+MLP epilogue: one thread per row
    if (tid < RPB) {
        int row = rowbase + tid;
        float x0[10];
#pragma unroll
        for (int j = 0; j < 10; ++j) {
            float d = dsum[tid * 10 + j] + pre0s[tid * 10 + j];
            x0[j] = fmaxf(fmaf(d, epi[j], epi[10 + j]), 0.f);
        }
        float sc = epi[85];
#pragma unroll
        for (int i = 0; i < 5; ++i) {
            float z = 0.f;
#pragma unroll
            for (int j = 0; j < 10; ++j)
                z = fmaf(x0[j], epi[30 + j * 5 + i], z);
            float x1 = fmaxf(fmaf(z, epi[20 + i], epi[25 + i]), 0.f);
            sc = fmaf(x1, epi[80 + i], sc);
        }
        g_scores[row] = sc;
    }
}

// ---------------------------------------------------------------------------
// K2a: partial max over 1024 scores per block (32 blocks)
// ---------------------------------------------------------------------------
__global__ void max_kernel()
{
    __shared__ float sred[256];
    int tid = threadIdx.x;
    float4 v = reinterpret_cast<const float4*>(g_scores)[blockIdx.x * 256 + tid];
    float m = fmaxf(fmaxf(v.x, v.y), fmaxf(v.z, v.w));
    sred[tid] = m;
    __syncthreads();
    for (int s = 128; s > 0; s >>= 1) {
        if (tid < s) sred[tid] = fmaxf(sred[tid], sred[tid + s]);
        __syncthreads();
    }
    if (tid == 0) g_pmax[blockIdx.x] = sred[0];
}

// ---------------------------------------------------------------------------
// K2b: partial sum of exp(v - M) per block (32 blocks); M derived identically
// in every block from the 32 partial maxes (deterministic).
// ---------------------------------------------------------------------------
__global__ void expsum_kernel()
{
    __shared__ float sred[256];
    int tid = threadIdx.x;
    float M = g_pmax[0];
#pragma unroll
    for (int i = 1; i < 32; ++i) M = fmaxf(M, g_pmax[i]);

    float4 v = reinterpret_cast<const float4*>(g_scores)[blockIdx.x * 256 + tid];
    float s = expf(v.x - M) + expf(v.y - M) + expf(v.z - M) + expf(v.w - M);
    sred[tid] = s;
    __syncthreads();
    for (int k = 128; k > 0; k >>= 1) {
        if (tid < k) sred[tid] += sred[tid + k];
        __syncthreads();
    }
    if (tid == 0) g_psum[blockIdx.x] = sred[0];
}

// ---------------------------------------------------------------------------
// K2c: w[tau] = exp(score[tau] - M) / S  for tau < 512
// ---------------------------------------------------------------------------
__global__ void weights_kernel()
{
    int tid = threadIdx.x;
    float M = g_pmax[0];
    float S = 0.f;
#pragma unroll
    for (int i = 1; i < 32; ++i) M = fmaxf(M, g_pmax[i]);
#pragma unroll
    for (int i = 0; i < 32; ++i) S += g_psum[i];
    g_w[tid] = expf(g_scores[tid] - M) * (1.0f / S);
}

// ---------------------------------------------------------------------------
// K3: ci[b,:] = sum_tau w[tau] * h[tau,b,:]
// grid (8 chunks of 128 cols, 64 b) x 256 threads.
// One t-line per warp per iteration -> 512B fully-coalesced warp loads.
// ---------------------------------------------------------------------------
__global__ __launch_bounds__(256)
void wsum_kernel(const float* __restrict__ h, float* __restrict__ out)
{
    __shared__ float ws[T_DIM];
    __shared__ float part[8][128];

    int tid  = threadIdx.x;
    int w    = tid >> 5;
    int lane = tid & 31;
    int c = blockIdx.x;           // 128-col chunk
    int b = blockIdx.y;

    if (tid < 128)
        reinterpret_cast<float4*>(ws)[tid] = reinterpret_cast<const float4*>(g_w)[tid];
    __syncthreads();

    const float* hp = h + (size_t)b * 1024 + c * 128 + 4 * lane;
    float4 acc = make_float4(0.f, 0.f, 0.f, 0.f);
#pragma unroll 8
    for (int t = w; t < T_DIM; t += 8) {
        float4 hv = *reinterpret_cast<const float4*>(hp + (size_t)t * (B_DIM * HU));
        float wv = ws[t];
        acc.x = fmaf(wv, hv.x, acc.x);
        acc.y = fmaf(wv, hv.y, acc.y);
        acc.z = fmaf(wv, hv.z, acc.z);
        acc.w = fmaf(wv, hv.w, acc.w);
    }
    *reinterpret_cast<float4*>(&part[w][4 * lane]) = acc;
    __syncthreads();

    if (tid < 128) {
        float s = part[0][tid];
#pragma unroll
        for (int q = 1; q < 8; ++q) s += part[q][tid];
        out[b * 1024 + c * 128 + tid] = s;
    }
}

// ---------------------------------------------------------------------------
extern "C" void kernel_launch(void* const* d_in, const int* in_sizes, int n_in,
                              void* d_out, int out_size)
{
    const float* si  = (const float*)d_in[0];
    const float* h   = (const float*)d_in[1];
    const float* W0  = (const float*)d_in[2];
    const float* b0  = (const float*)d_in[3];
    const float* g0  = (const float*)d_in[4];
    const float* be0 = (const float*)d_in[5];
    const float* m0  = (const float*)d_in[6];
    const float* v0  = (const float*)d_in[7];
    const float* W1  = (const float*)d_in[8];
    const float* b1  = (const float*)d_in[9];
    const float* g1  = (const float*)d_in[10];
    const float* be1 = (const float*)d_in[11];
    const float* m1  = (const float*)d_in[12];
    const float* v1  = (const float*)d_in[13];
    const float* W2  = (const float*)d_in[14];
    const float* b2  = (const float*)d_in[15];
    float* out = (float*)d_out;

    prep_kernel<<<B_DIM, 320>>>(si, W0, b0, g0, be0, m0, v0, b1, g1, be1, m1, v1);
    score_kernel<<<NROWS / RPB, 256>>>(h, W0, W1, W2, b2);
    max_kernel<<<32, 256>>>();
    expsum_kernel<<<32, 256>>>();
    weights_kernel<<<1, T_DIM>>>();
    wsum_kernel<<<dim3(8, B_DIM), 256>>>(h, out);
}

// round 3
// speedup vs baseline: 1.1480x; 1.0663x over previous
#include <cuda_runtime.h>
#include <cuda_bf16.h>
#include <math.h>

// ----------------------------------------------------------------------------
// Attention_13314398617962   (t=512, b=64, s=1024, hu=1024)
//   scores[t,b] = MLP(concat(si[b], h[t,b]))   (2048 -> 10 -> 5 -> 1, BN+relu)
//   a = softmax(scores.flatten())              (over all 32768)
//   ci[b,:] = sum_tau a[tau] * h[tau, b, :]    (tau < 512)
// ----------------------------------------------------------------------------

#define T_DIM 512
#define B_DIM 64
#define HU 1024
#define NROWS (T_DIM * B_DIM)   // 32768
#define RPB 16                  // rows per block in score kernel
#define NBLK (NROWS / RPB)      // 2048

__device__ float g_pre0[B_DIM * 10];   // si @ W0[:1024] per b  (includes nothing else)
__device__ float g_ep[30];             // s0[10] t0[10] s1[5] t1[5]
__device__ float g_scores[T_DIM];      // raw scores, only rows < 512 needed
__device__ float g_w[T_DIM];           // softmax weights for tau < 512
__device__ float g_bmax[NBLK];
__device__ float g_bsum[NBLK];

// ---------------------------------------------------------------------------
__device__ __forceinline__ void ffma2(unsigned long long& d,
                                      unsigned long long a,
                                      unsigned long long b)
{
    asm("fma.rn.f32x2 %0, %1, %2, %0;" : "+l"(d) : "l"(a), "l"(b));
}
__device__ __forceinline__ unsigned long long pack2(float x)
{
    unsigned long long r;
    asm("mov.b64 %0, {%1, %1};" : "=l"(r) : "f"(x));
    return r;
}
__device__ __forceinline__ void unpack2(unsigned long long v, float& lo, float& hi)
{
    asm("mov.b64 {%0, %1}, %2;" : "=f"(lo), "=f"(hi) : "l"(v));
}

// ---------------------------------------------------------------------------
// K0: per-b si contribution + folded BN constants
// ---------------------------------------------------------------------------
__global__ void prep_kernel(const float* __restrict__ si,
                            const float* __restrict__ W0,
                            const float* __restrict__ b0,
                            const float* __restrict__ g0,
                            const float* __restrict__ be0,
                            const float* __restrict__ m0,
                            const float* __restrict__ v0,
                            const float* __restrict__ b1,
                            const float* __restrict__ g1,
                            const float* __restrict__ be1,
                            const float* __restrict__ m1,
                            const float* __restrict__ v1)
{
    int b = blockIdx.x;
    int tid = threadIdx.x;
    int w = tid >> 5;     // 0..9 = output column
    int l = tid & 31;

    const float* sb = si + b * 1024;
    float acc = 0.f;
#pragma unroll 8
    for (int i = 0; i < 32; ++i) {
        int k = l + (i << 5);
        acc = fmaf(sb[k], W0[k * 10 + w], acc);
    }
#pragma unroll
    for (int o = 16; o > 0; o >>= 1)
        acc += __shfl_xor_sync(0xffffffffu, acc, o);
    if (l == 0) g_pre0[b * 10 + w] = acc;

    if (b == 0) {
        if (tid < 10) {
            float s = g0[tid] * (1.0f / sqrtf(v0[tid] + 1e-5f));
            g_ep[tid] = s;
            g_ep[10 + tid] = (b0[tid] - m0[tid]) * s + be0[tid];
        } else if (tid >= 16 && tid < 21) {
            int i = tid - 16;
            float s = g1[i] * (1.0f / sqrtf(v1[i] + 1e-5f));
            g_ep[20 + i] = s;
            g_ep[25 + i] = (b1[i] - m1[i]) * s + be1[i];
        }
    }
}

// ---------------------------------------------------------------------------
// K1: scores + per-block online softmax stats.
// 256 threads, 16 rows/block. Thread owns k = 4*tid..4*tid+3 (40 weight
// floats as 20 packed f32x2 regs). Hot loop: 1 float4 load, 4 packs,
// 20 FFMA2, 20 SHFL, predicated 10-float STS. No barrier in loop.
// End: block reduce (64 partials per (row,j)), 16-thread MLP epilogue,
// warp-0 online max/exp-sum over the block's 16 scores.
// ---------------------------------------------------------------------------
__global__ __launch_bounds__(256, 3)
void score_kernel(const float* __restrict__ h,
                  const float* __restrict__ W0,
                  const float* __restrict__ W1,
                  const float* __restrict__ W2,
                  const float* __restrict__ b2)
{
    __shared__ float red[RPB * 64 * 10];      // [it][part][j]  40 KB
    __shared__ float pre0s[RPB * 10];
    __shared__ float dsum[RPB * 10];
    __shared__ float epi[86];                 // s0 t0 s1 t1 W1[50] W2[5] b2

    int tid  = threadIdx.x;
    int lane = tid & 31;
    int warp = tid >> 5;
    int rowbase = blockIdx.x * RPB;
    int bbase   = rowbase & 63;

    if (tid < 30)                  epi[tid] = g_ep[tid];
    if (tid >= 32 && tid < 82)     epi[30 + tid - 32] = W1[tid - 32];
    if (tid >= 96 && tid < 101)    epi[80 + tid - 96] = W2[tid - 96];
    if (tid == 101)                epi[85] = b2[0];
    if (tid < RPB * 10)            pre0s[tid] = g_pre0[bbase * 10 + tid];

    // 40 weight floats = 20 packed f32x2: u[kk*5+p] = (W0[gk][2p], W0[gk][2p+1])
    union { float4 v[10]; unsigned long long u[20]; } wr;
    {
        const float4* wp = reinterpret_cast<const float4*>(W0 + (1024 + 4 * tid) * 10);
#pragma unroll
        for (int i = 0; i < 10; ++i) wr.v[i] = wp[i];
    }

    const float* hb = h + (size_t)rowbase * 1024 + 4 * tid;
    float4 P0 = *reinterpret_cast<const float4*>(hb);
    float4 P1 = *reinterpret_cast<const float4*>(hb + 1024);

    __syncthreads();   // smem staging visible (pre0s/epi used later; barrier here is free)

#pragma unroll 4
    for (int it = 0; it < RPB; ++it) {
        float4 cv = P0;
        P0 = P1;
        if (it < RPB - 2)
            P1 = *reinterpret_cast<const float4*>(hb + (size_t)(it + 2) * 1024);

        unsigned long long acc[5];
        unsigned long long hh;
        hh = pack2(cv.x);
#pragma unroll
        for (int p = 0; p < 5; ++p) {
            asm("mul.rn.f32x2 %0, %1, %2;" : "=l"(acc[p]) : "l"(hh), "l"(wr.u[p]));
        }
        hh = pack2(cv.y);
#pragma unroll
        for (int p = 0; p < 5; ++p) ffma2(acc[p], hh, wr.u[5 + p]);
        hh = pack2(cv.z);
#pragma unroll
        for (int p = 0; p < 5; ++p) ffma2(acc[p], hh, wr.u[10 + p]);
        hh = pack2(cv.w);
#pragma unroll
        for (int p = 0; p < 5; ++p) ffma2(acc[p], hh, wr.u[15 + p]);

        float pj[10];
#pragma unroll
        for (int p = 0; p < 5; ++p) unpack2(acc[p], pj[2 * p], pj[2 * p + 1]);

#pragma unroll
        for (int j = 0; j < 10; ++j) {
            pj[j] += __shfl_xor_sync(0xffffffffu, pj[j], 16);
            pj[j] += __shfl_xor_sync(0xffffffffu, pj[j], 8);
        }
        if (lane < 8) {
            float* rb = red + (it * 64 + warp * 8 + lane) * 10;
#pragma unroll
            for (int j = 0; j < 10; ++j) rb[j] = pj[j];
        }
    }
    __syncthreads();

    // block reduce: 160 (row,j) sums, each over 64 partials
    if (tid < RPB * 10) {
        int rl = tid / 10;
        int j  = tid - rl * 10;
        const float* base = red + (rl * 64) * 10 + j;
        float s = 0.f;
#pragma unroll
        for (int q = 0; q < 64; ++q) s += base[q * 10];
        dsum[tid] = s;
    }
    __syncthreads();

    // fused MLP epilogue + per-block online softmax stats (warp 0)
    if (tid < 32) {
        float sc = -1e30f;
        if (tid < RPB) {
            int row = rowbase + tid;
            float x0[10];
#pragma unroll
            for (int j = 0; j < 10; ++j) {
                float d = dsum[tid * 10 + j] + pre0s[tid * 10 + j];
                x0[j] = fmaxf(fmaf(d, epi[j], epi[10 + j]), 0.f);
            }
            sc = epi[85];
#pragma unroll
            for (int i = 0; i < 5; ++i) {
                float z = 0.f;
#pragma unroll
                for (int j = 0; j < 10; ++j)
                    z = fmaf(x0[j], epi[30 + j * 5 + i], z);
                float x1 = fmaxf(fmaf(z, epi[20 + i], epi[25 + i]), 0.f);
                sc = fmaf(x1, epi[80 + i], sc);
            }
            if (row < T_DIM) g_scores[row] = sc;
        }
        float m = sc;
#pragma unroll
        for (int o = 16; o > 0; o >>= 1)
            m = fmaxf(m, __shfl_xor_sync(0xffffffffu, m, o));
        float e = (tid < RPB) ? expf(sc - m) : 0.f;
#pragma unroll
        for (int o = 16; o > 0; o >>= 1)
            e += __shfl_xor_sync(0xffffffffu, e, o);
        if (tid == 0) {
            g_bmax[blockIdx.x] = m;
            g_bsum[blockIdx.x] = e;
        }
    }
}

// ---------------------------------------------------------------------------
// K2: combine 2048 (max, expsum) pairs -> M, S; write 512 weights.
// Single block, 512 threads, fixed-order reductions (deterministic).
// ---------------------------------------------------------------------------
__global__ void combine_kernel()
{
    __shared__ float sm[512];
    __shared__ float MS[2];
    int tid = threadIdx.x;

    float lm = -1e30f;
#pragma unroll
    for (int i = 0; i < 4; ++i) lm = fmaxf(lm, g_bmax[tid * 4 + i]);
    sm[tid] = lm;
    __syncthreads();
    for (int s = 256; s > 0; s >>= 1) {
        if (tid < s) sm[tid] = fmaxf(sm[tid], sm[tid + s]);
        __syncthreads();
    }
    if (tid == 0) MS[0] = sm[0];
    __syncthreads();
    float M = MS[0];

    float ls = 0.f;
#pragma unroll
    for (int i = 0; i < 4; ++i)
        ls += g_bsum[tid * 4 + i] * expf(g_bmax[tid * 4 + i] - M);
    sm[tid] = ls;
    __syncthreads();
    for (int s = 256; s > 0; s >>= 1) {
        if (tid < s) sm[tid] += sm[tid + s];
        __syncthreads();
    }
    if (tid == 0) MS[1] = 1.0f / sm[0];
    __syncthreads();

    g_w[tid] = expf(g_scores[tid] - M) * MS[1];
}

// ---------------------------------------------------------------------------
// K3: ci[b,:] = sum_tau w[tau] * h[tau,b,:]
// Iterates t in REVERSE so the tail of h (still resident in L2 from the
// score pass) is read before eviction -> converts streaming misses to hits.
// grid (8 chunks of 128 cols, 64 b) x 256 threads.
// ---------------------------------------------------------------------------
__global__ __launch_bounds__(256)
void wsum_kernel(const float* __restrict__ h, float* __restrict__ out)
{
    __shared__ float ws[T_DIM];
    __shared__ float part[8][128];

    int tid  = threadIdx.x;
    int w    = tid >> 5;
    int lane = tid & 31;
    int c = blockIdx.x;           // 128-col chunk
    int b = blockIdx.y;

    if (tid < 128)
        reinterpret_cast<float4*>(ws)[tid] = reinterpret_cast<const float4*>(g_w)[tid];
    __syncthreads();

    const float* hp = h + (size_t)b * 1024 + c * 128 + 4 * lane;
    float4 acc = make_float4(0.f, 0.f, 0.f, 0.f);
#pragma unroll 8
    for (int i = 0; i < T_DIM / 8; ++i) {
        int t = T_DIM - 1 - (i * 8 + w);
        float4 hv = *reinterpret_cast<const float4*>(hp + (size_t)t * (B_DIM * HU));
        float wv = ws[t];
        acc.x = fmaf(wv, hv.x, acc.x);
        acc.y = fmaf(wv, hv.y, acc.y);
        acc.z = fmaf(wv, hv.z, acc.z);
        acc.w = fmaf(wv, hv.w, acc.w);
    }
    *reinterpret_cast<float4*>(&part[w][4 * lane]) = acc;
    __syncthreads();

    if (tid < 128) {
        float s = part[0][tid];
#pragma unroll
        for (int q = 1; q < 8; ++q) s += part[q][tid];
        out[b * 1024 + c * 128 + tid] = s;
    }
}

// ---------------------------------------------------------------------------
extern "C" void kernel_launch(void* const* d_in, const int* in_sizes, int n_in,
                              void* d_out, int out_size)
{
    const float* si  = (const float*)d_in[0];
    const float* h   = (const float*)d_in[1];
    const float* W0  = (const float*)d_in[2];
    const float* b0  = (const float*)d_in[3];
    const float* g0  = (const float*)d_in[4];
    const float* be0 = (const float*)d_in[5];
    const float* m0  = (const float*)d_in[6];
    const float* v0  = (const float*)d_in[7];
    const float* W1  = (const float*)d_in[8];
    const float* b1  = (const float*)d_in[9];
    const float* g1  = (const float*)d_in[10];
    const float* be1 = (const float*)d_in[11];
    const float* m1  = (const float*)d_in[12];
    const float* v1  = (const float*)d_in[13];
    const float* W2  = (const float*)d_in[14];
    const float* b2  = (const float*)d_in[15];
    float* out = (float*)d_out;

    prep_kernel<<<B_DIM, 320>>>(si, W0, b0, g0, be0, m0, v0, b1, g1, be1, m1, v1);
    score_kernel<<<NBLK, 256>>>(h, W0, W1, W2, b2);
    combine_kernel<<<1, 512>>>();
    wsum_kernel<<<dim3(8, B_DIM), 256>>>(h, out);
}

// round 4
// speedup vs baseline: 1.2105x; 1.0544x over previous
#include <cuda_runtime.h>
#include <cuda_bf16.h>
#include <math.h>

// ----------------------------------------------------------------------------
// Attention_13314398617962   (t=512, b=64, s=1024, hu=1024)
//   scores[t,b] = MLP(concat(si[b], h[t,b]))   (2048 -> 10 -> 5 -> 1, BN+relu)
//   a = softmax(scores.flatten())              (over all 32768)
//   ci[b,:] = sum_tau a[tau] * h[tau_t, tau_b, :]   (tau < 512)
// ----------------------------------------------------------------------------

#define T_DIM 512
#define B_DIM 64
#define HU 1024
#define NROWS (T_DIM * B_DIM)   // 32768
#define RPB 32                  // rows per block in score kernel
#define NBLK (NROWS / RPB)      // 1024

__device__ float g_pre0[B_DIM * 10];   // si @ W0[:1024] per b (raw dot)
__device__ float g_ep[30];             // s0[10] t0[10] s1[5] t1[5]
__device__ float g_scores[T_DIM];      // raw scores for rows < 512
__device__ float g_w[T_DIM];           // softmax weights
__device__ float g_bmax[NBLK];
__device__ float g_bsum[NBLK];

// ---------------------------------------------------------------------------
__device__ __forceinline__ void ffma2(unsigned long long& d,
                                      unsigned long long a,
                                      unsigned long long b)
{
    asm("fma.rn.f32x2 %0, %1, %2, %0;" : "+l"(d) : "l"(a), "l"(b));
}
__device__ __forceinline__ void fmul2(unsigned long long& d,
                                      unsigned long long a,
                                      unsigned long long b)
{
    asm("mul.rn.f32x2 %0, %1, %2;" : "=l"(d) : "l"(a), "l"(b));
}
__device__ __forceinline__ unsigned long long pack2(float x)
{
    unsigned long long r;
    asm("mov.b64 %0, {%1, %1};" : "=l"(r) : "f"(x));
    return r;
}
__device__ __forceinline__ void unpack2(unsigned long long v, float& lo, float& hi)
{
    asm("mov.b64 {%0, %1}, %2;" : "=f"(lo), "=f"(hi) : "l"(v));
}

// ---------------------------------------------------------------------------
// K0: per-b si contribution (coalesced W0 reads) + folded BN constants.
// 64 blocks x 256 threads. Thread owns k = 4*tid..4*tid+3; W0 rows are
// 40 consecutive floats -> contiguous warp traffic.
// ---------------------------------------------------------------------------
__global__ __launch_bounds__(256)
void prep_kernel(const float* __restrict__ si,
                 const float* __restrict__ W0,
                 const float* __restrict__ b0,
                 const float* __restrict__ g0,
                 const float* __restrict__ be0,
                 const float* __restrict__ m0,
                 const float* __restrict__ v0,
                 const float* __restrict__ b1,
                 const float* __restrict__ g1,
                 const float* __restrict__ be1,
                 const float* __restrict__ m1,
                 const float* __restrict__ v1)
{
    __shared__ float red[64][10];

    int b = blockIdx.x;
    int tid = threadIdx.x;
    int lane = tid & 31;
    int warp = tid >> 5;

    // 40 weight floats (W0 rows 4*tid..4*tid+3, si half)
    float wv[40];
    {
        const float4* wp = reinterpret_cast<const float4*>(W0 + 4 * tid * 10);
#pragma unroll
        for (int i = 0; i < 10; ++i)
            reinterpret_cast<float4*>(wv)[i] = wp[i];
    }
    float4 sv = reinterpret_cast<const float4*>(si + b * 1024)[tid];

    float pj[10];
#pragma unroll
    for (int j = 0; j < 10; ++j) {
        float a = sv.x * wv[j];
        a = fmaf(sv.y, wv[10 + j], a);
        a = fmaf(sv.z, wv[20 + j], a);
        a = fmaf(sv.w, wv[30 + j], a);
        pj[j] = a;
    }
#pragma unroll
    for (int j = 0; j < 10; ++j) {
        pj[j] += __shfl_xor_sync(0xffffffffu, pj[j], 16);
        pj[j] += __shfl_xor_sync(0xffffffffu, pj[j], 8);
    }
    if (lane < 8) {
#pragma unroll
        for (int j = 0; j < 10; ++j) red[warp * 8 + lane][j] = pj[j];
    }
    __syncthreads();

    if (tid < 10) {
        float s = 0.f;
#pragma unroll
        for (int q = 0; q < 64; ++q) s += red[q][tid];
        g_pre0[b * 10 + tid] = s;
    }

    if (b == 0) {
        if (tid >= 32 && tid < 42) {
            int i = tid - 32;
            float s = g0[i] * (1.0f / sqrtf(v0[i] + 1e-5f));
            g_ep[i] = s;
            g_ep[10 + i] = (b0[i] - m0[i]) * s + be0[i];
        } else if (tid >= 64 && tid < 69) {
            int i = tid - 64;
            float s = g1[i] * (1.0f / sqrtf(v1[i] + 1e-5f));
            g_ep[20 + i] = s;
            g_ep[25 + i] = (b1[i] - m1[i]) * s + be1[i];
        }
    }
}

// ---------------------------------------------------------------------------
// K1: scores + per-block online softmax stats.
// 256 threads = 2 row-groups x 128. Thread owns 8 k (4*ts and 512+4*ts),
// weights as 40 packed f32x2 regs. Per row: 2 float4 loads, 8 packs,
// 40 FFMA2, 20 SHFL, 5 STS.64 (lane<8). No barrier in the 16-iter loop
// (distinct smem slot per iteration); one end barrier, block reduce,
// 32-thread MLP epilogue + warp-0 max/exp-sum.
// ---------------------------------------------------------------------------
__global__ __launch_bounds__(256, 2)
void score_kernel(const float* __restrict__ h,
                  const float* __restrict__ W0,
                  const float* __restrict__ W1,
                  const float* __restrict__ W2,
                  const float* __restrict__ b2)
{
    __shared__ float red[2 * 16 * 32 * 10];   // [g][it][part][j]  40 KB
    __shared__ float pre0s[RPB * 10];
    __shared__ float dsum[RPB * 10];
    __shared__ float epi[86];                 // s0 t0 s1 t1 W1[50] W2[5] b2

    int tid  = threadIdx.x;
    int g    = tid >> 7;
    int ts   = tid & 127;
    int lane = tid & 31;
    int wl   = (tid >> 5) & 3;                // warp within group
    int rowbase = blockIdx.x * RPB;
    int bbase   = rowbase & 63;

    if (tid < 30)                  epi[tid] = g_ep[tid];
    if (tid >= 32 && tid < 82)     epi[30 + tid - 32] = W1[tid - 32];
    if (tid >= 96 && tid < 101)    epi[80 + tid - 96] = W2[tid - 96];
    if (tid == 101)                epi[85] = b2[0];
    pre0s[tid] = g_pre0[bbase * 10 + tid];
    if (tid < 64) pre0s[256 + tid] = g_pre0[bbase * 10 + 256 + tid];

    // 80 weight floats as 40 packed f32x2: u[kk*5+p]
    union { float4 v[20]; unsigned long long u[40]; } wr;
    {
        const float4* wp0 = reinterpret_cast<const float4*>(W0 + (1024 + 4 * ts) * 10);
        const float4* wp1 = reinterpret_cast<const float4*>(W0 + (1536 + 4 * ts) * 10);
#pragma unroll
        for (int i = 0; i < 10; ++i) wr.v[i] = wp0[i];
#pragma unroll
        for (int i = 0; i < 10; ++i) wr.v[10 + i] = wp1[i];
    }

    const float* hb = h + (size_t)(rowbase + g) * 1024 + 4 * ts;
    float4 A0 = *reinterpret_cast<const float4*>(hb);
    float4 B0 = *reinterpret_cast<const float4*>(hb + 512);
    float4 A1 = *reinterpret_cast<const float4*>(hb + 2048);
    float4 B1 = *reinterpret_cast<const float4*>(hb + 2048 + 512);

    __syncthreads();   // smem staging visible

    float* myred = red + ((g * 16) * 32 + wl * 8 + lane) * 10;

#pragma unroll 4
    for (int it = 0; it < 16; ++it) {
        float4 ca = A0, cb = B0;
        A0 = A1; B0 = B1;
        if (it < 14) {
            const float* pn = hb + (size_t)(it + 2) * 2048;
            A1 = *reinterpret_cast<const float4*>(pn);
            B1 = *reinterpret_cast<const float4*>(pn + 512);
        }

        unsigned long long acc[5];
        unsigned long long hh;
        hh = pack2(ca.x);
#pragma unroll
        for (int p = 0; p < 5; ++p) fmul2(acc[p], hh, wr.u[p]);
        hh = pack2(ca.y);
#pragma unroll
        for (int p = 0; p < 5; ++p) ffma2(acc[p], hh, wr.u[5 + p]);
        hh = pack2(ca.z);
#pragma unroll
        for (int p = 0; p < 5; ++p) ffma2(acc[p], hh, wr.u[10 + p]);
        hh = pack2(ca.w);
#pragma unroll
        for (int p = 0; p < 5; ++p) ffma2(acc[p], hh, wr.u[15 + p]);
        hh = pack2(cb.x);
#pragma unroll
        for (int p = 0; p < 5; ++p) ffma2(acc[p], hh, wr.u[20 + p]);
        hh = pack2(cb.y);
#pragma unroll
        for (int p = 0; p < 5; ++p) ffma2(acc[p], hh, wr.u[25 + p]);
        hh = pack2(cb.z);
#pragma unroll
        for (int p = 0; p < 5; ++p) ffma2(acc[p], hh, wr.u[30 + p]);
        hh = pack2(cb.w);
#pragma unroll
        for (int p = 0; p < 5; ++p) ffma2(acc[p], hh, wr.u[35 + p]);

        float pj[10];
#pragma unroll
        for (int p = 0; p < 5; ++p) unpack2(acc[p], pj[2 * p], pj[2 * p + 1]);

#pragma unroll
        for (int j = 0; j < 10; ++j) {
            pj[j] += __shfl_xor_sync(0xffffffffu, pj[j], 16);
            pj[j] += __shfl_xor_sync(0xffffffffu, pj[j], 8);
        }
        if (lane < 8) {
            float2* rb = reinterpret_cast<float2*>(myred + it * 320);
#pragma unroll
            for (int p = 0; p < 5; ++p) rb[p] = make_float2(pj[2 * p], pj[2 * p + 1]);
        }
    }
    __syncthreads();

    // block reduce: 320 (row,j) sums, each over 32 partials (stride 10 floats)
#pragma unroll
    for (int pass = 0; pass < 2; ++pass) {
        int m = tid + pass * 256;
        if (m < 320) {
            int gg = m / 160;
            int rem = m - gg * 160;
            int rl = rem / 10;
            int j = rem - rl * 10;
            const float* base = red + ((gg * 16 + rl) * 32) * 10 + j;
            float s0 = 0.f, s1 = 0.f, s2 = 0.f, s3 = 0.f;
#pragma unroll
            for (int q = 0; q < 8; ++q) {
                s0 += base[(4 * q) * 10];
                s1 += base[(4 * q + 1) * 10];
                s2 += base[(4 * q + 2) * 10];
                s3 += base[(4 * q + 3) * 10];
            }
            dsum[(2 * rl + gg) * 10 + j] = (s0 + s1) + (s2 + s3);
        }
    }
    __syncthreads();

    // fused MLP epilogue + per-block online softmax stats (warp 0, 32 rows)
    if (tid < 32) {
        int row = rowbase + tid;
        float x0[10];
#pragma unroll
        for (int j = 0; j < 10; ++j) {
            float d = dsum[tid * 10 + j] + pre0s[tid * 10 + j];
            x0[j] = fmaxf(fmaf(d, epi[j], epi[10 + j]), 0.f);
        }
        float sc = epi[85];
#pragma unroll
        for (int i = 0; i < 5; ++i) {
            float z = 0.f;
#pragma unroll
            for (int j = 0; j < 10; ++j)
                z = fmaf(x0[j], epi[30 + j * 5 + i], z);
            float x1 = fmaxf(fmaf(z, epi[20 + i], epi[25 + i]), 0.f);
            sc = fmaf(x1, epi[80 + i], sc);
        }
        if (row < T_DIM) g_scores[row] = sc;

        float m = sc;
#pragma unroll
        for (int o = 16; o > 0; o >>= 1)
            m = fmaxf(m, __shfl_xor_sync(0xffffffffu, m, o));
        float e = expf(sc - m);
#pragma unroll
        for (int o = 16; o > 0; o >>= 1)
            e += __shfl_xor_sync(0xffffffffu, e, o);
        if (tid == 0) {
            g_bmax[blockIdx.x] = m;
            g_bsum[blockIdx.x] = e;
        }
    }
}

// ---------------------------------------------------------------------------
// K2: combine 1024 (max, expsum) pairs -> M, S; write 512 weights.
// Single block, 512 threads, fixed-order reductions (deterministic).
// ---------------------------------------------------------------------------
__global__ void combine_kernel()
{
    __shared__ float sm[512];
    __shared__ float MS[2];
    int tid = threadIdx.x;

    float m0v = g_bmax[tid * 2];
    float m1v = g_bmax[tid * 2 + 1];
    sm[tid] = fmaxf(m0v, m1v);
    __syncthreads();
    for (int s = 256; s > 0; s >>= 1) {
        if (tid < s) sm[tid] = fmaxf(sm[tid], sm[tid + s]);
        __syncthreads();
    }
    if (tid == 0) MS[0] = sm[0];
    __syncthreads();
    float M = MS[0];

    float ls = g_bsum[tid * 2] * expf(m0v - M)
             + g_bsum[tid * 2 + 1] * expf(m1v - M);
    sm[tid] = ls;
    __syncthreads();
    for (int s = 256; s > 0; s >>= 1) {
        if (tid < s) sm[tid] += sm[tid + s];
        __syncthreads();
    }
    if (tid == 0) MS[1] = 1.0f / sm[0];
    __syncthreads();

    g_w[tid] = expf(g_scores[tid] - M) * MS[1];
}

// ---------------------------------------------------------------------------
// K3: ci[b,:] = sum_tau w[tau] * h[tau,b,:]
// grid (8 chunks of 128 cols, 64 b) x 512 threads (16 warps, t == w mod 16).
// ---------------------------------------------------------------------------
__global__ __launch_bounds__(512)
void wsum_kernel(const float* __restrict__ h, float* __restrict__ out)
{
    __shared__ float ws[T_DIM];
    __shared__ float part[16][128];

    int tid  = threadIdx.x;
    int w    = tid >> 5;
    int lane = tid & 31;
    int c = blockIdx.x;           // 128-col chunk
    int b = blockIdx.y;

    if (tid < 128)
        reinterpret_cast<float4*>(ws)[tid] = reinterpret_cast<const float4*>(g_w)[tid];
    __syncthreads();

    const float* hp = h + (size_t)b * 1024 + c * 128 + 4 * lane;
    float4 acc = make_float4(0.f, 0.f, 0.f, 0.f);
#pragma unroll 8
    for (int i = 0; i < T_DIM / 16; ++i) {
        int t = i * 16 + w;
        float4 hv = *reinterpret_cast<const float4*>(hp + (size_t)t * (B_DIM * HU));
        float wv = ws[t];
        acc.x = fmaf(wv, hv.x, acc.x);
        acc.y = fmaf(wv, hv.y, acc.y);
        acc.z = fmaf(wv, hv.z, acc.z);
        acc.w = fmaf(wv, hv.w, acc.w);
    }
    *reinterpret_cast<float4*>(&part[w][4 * lane]) = acc;
    __syncthreads();

    if (tid < 128) {
        float s0 = part[0][tid], s1 = part[1][tid];
        float s2 = part[2][tid], s3 = part[3][tid];
#pragma unroll
        for (int q = 4; q < 16; q += 4) {
            s0 += part[q][tid];
            s1 += part[q + 1][tid];
            s2 += part[q + 2][tid];
            s3 += part[q + 3][tid];
        }
        out[b * 1024 + c * 128 + tid] = (s0 + s1) + (s2 + s3);
    }
}

// ---------------------------------------------------------------------------
extern "C" void kernel_launch(void* const* d_in, const int* in_sizes, int n_in,
                              void* d_out, int out_size)
{
    const float* si  = (const float*)d_in[0];
    const float* h   = (const float*)d_in[1];
    const float* W0  = (const float*)d_in[2];
    const float* b0  = (const float*)d_in[3];
    const float* g0  = (const float*)d_in[4];
    const float* be0 = (const float*)d_in[5];
    const float* m0  = (const float*)d_in[6];
    const float* v0  = (const float*)d_in[7];
    const float* W1  = (const float*)d_in[8];
    const float* b1  = (const float*)d_in[9];
    const float* g1  = (const float*)d_in[10];
    const float* be1 = (const float*)d_in[11];
    const float* m1  = (const float*)d_in[12];
    const float* v1  = (const float*)d_in[13];
    const float* W2  = (const float*)d_in[14];
    const float* b2  = (const float*)d_in[15];
    float* out = (float*)d_out;

    prep_kernel<<<B_DIM, 256>>>(si, W0, b0, g0, be0, m0, v0, b1, g1, be1, m1, v1);
    score_kernel<<<NBLK, 256>>>(h, W0, W1, W2, b2);
    combine_kernel<<<1, 512>>>();
    wsum_kernel<<<dim3(8, B_DIM), 512>>>(h, out);
}